// round 11
// baseline (speedup 1.0000x reference)
#include <cuda_runtime.h>

#define TPB     384
#define NODES   96
#define KU      8                   // u per chunk
#define NCHUNK  16
#define XS      76                  // per node per chunk: x0(8)+x1(24)+x2(40)+pad(4)
#define XBUF    (NODES * XS)        // 7296 floats per buffer
#define OFF_W1  (3 * XBUF)          // 21888 (w1_1: 2048 floats)
#define OFF_W2  (OFF_W1 + 2048)    // 23936 (w1_2: 2048)
#define SM_FLOATS (OFF_W2 + 2048)  // 25984 floats = 103936 B -> 2 blocks/SM

typedef unsigned long long u64;

__device__ __forceinline__ u64 ffma2(u64 a, u64 b, u64 c) {
    u64 d;
    asm("fma.rn.f32x2 %0, %1, %2, %3;" : "=l"(d) : "l"(a), "l"(b), "l"(c));
    return d;
}
__device__ __forceinline__ u64 dup2(float v) {
    u64 d; unsigned u = __float_as_uint(v);
    asm("mov.b64 %0, {%1, %1};" : "=l"(d) : "r"(u));
    return d;
}
__device__ __forceinline__ void unpack2(u64 a, float& lo, float& hi) {
    lo = __uint_as_float((unsigned)a);
    hi = __uint_as_float((unsigned)(a >> 32));
}
__device__ __forceinline__ float silu(float v) {
    return v / (1.f + __expf(-v));
}

__global__ void __launch_bounds__(TPB, 2)
readout_kernel(const float* __restrict__ x,
               const float* __restrict__ w1_0, const float* __restrict__ w1_1,
               const float* __restrict__ w1_2, const float* __restrict__ w2_0,
               const float* __restrict__ w2_1, const float* __restrict__ w2_2,
               float* __restrict__ out, int n)
{
    extern __shared__ float sm[];
    const int tid = threadIdx.x;
    const int node0 = blockIdx.x * NODES;
    const unsigned smbase = (unsigned)__cvta_generic_to_shared(sm);

    // ---- cp.async staging: 96 nodes x 18 float4 per chunk = 1728 over 384 thr ----
    int pk_goff[5], pk_sc[5];
    unsigned pk_dst[5];
#pragma unroll
    for (int k = 0; k < 5; ++k) {
        int f = tid + k * TPB;
        if (f >= 18 * NODES) { pk_goff[k] = -1; pk_sc[k] = 0; pk_dst[k] = 0; continue; }
        int nd = f / 18, r = f - nd * 18;
        int sb, sc, dl;
        if (r < 2)      { sb = 4 * r;             sc = 8;  dl = 4 * r; }
        else if (r < 8) { sb = 128 + 4 * (r - 2); sc = 24; dl = 8 + 4 * (r - 2); }
        else            { sb = 512 + 4 * (r - 8); sc = 40; dl = 32 + 4 * (r - 8); }
        int gn = node0 + nd;
        if (gn >= n) gn = n - 1;                 // clamp; output stores are guarded
        pk_goff[k] = gn * 1152 + sb;
        pk_sc[k]   = sc;
        pk_dst[k]  = (unsigned)((nd * XS + dl) * 4);
    }
    auto stage = [&](int c, int buf) {
#pragma unroll
        for (int k = 0; k < 5; ++k) {
            if (pk_goff[k] < 0) break;
            const float* src = x + pk_goff[k] + pk_sc[k] * c;
            unsigned dst = smbase + (unsigned)(buf * (XBUF * 4)) + pk_dst[k];
            asm volatile("cp.async.cg.shared.global [%0], [%1], 16;"
                         :: "r"(dst), "l"(src));
        }
    };

    // two chunks in flight before any compute
    stage(0, 0); asm volatile("cp.async.commit_group;" ::: "memory");
    stage(1, 1); asm volatile("cp.async.commit_group;" ::: "memory");

    // small weights to smem (covered by in-flight chunks); w1_0 stays in L1
    for (int i = tid; i < 2048; i += TPB) sm[OFF_W1 + i] = w1_1[i];
    for (int i = tid; i < 2048; i += TPB) sm[OFF_W2 + i] = w1_2[i];

    // 12 warps = 3 groups x 4 roles. SMSP0 gets the three role0 warps,
    // each other SMSP gets {role1, role2, role3} -> balanced issue load.
    const int w    = tid >> 5;
    const int lane = tid & 31;
    const int s    = w & 3;
    const int g    = w >> 2;
    const int role = (s == 0) ? 0 : (1 + ((g + s) % 3));
    const int node = g * 32 + lane;

    u64 A[24];
#pragma unroll
    for (int i = 0; i < 24; ++i) A[i] = 0ull;

#pragma unroll 1
    for (int c = 0; c < NCHUNK; ++c) {
        if (c == NCHUNK - 1) asm volatile("cp.async.wait_group 0;" ::: "memory");
        else                 asm volatile("cp.async.wait_group 1;" ::: "memory");
        __syncthreads();
        if (c + 2 < NCHUNK) {
            stage(c + 2, (c + 2) % 3);      // overwrites buffer (c-1)%3: safe past barrier
            asm volatile("cp.async.commit_group;" ::: "memory");
        }
        const float* xr = sm + (c % 3) * XBUF + node * XS;
        const int u0 = KU * c;

        if (role == 0) {
            // y0: ALL 48 outputs as 24 f32x2 pairs; weights via uniform L1 LDG
            float4 xa = *(const float4*)xr;
            float4 xb = *(const float4*)(xr + 4);
            float xe[8] = { xa.x, xa.y, xa.z, xa.w, xb.x, xb.y, xb.z, xb.w };
#pragma unroll
            for (int u = 0; u < 8; ++u) {
                u64 xs2 = dup2(xe[u]);
                const ulonglong2* wr =
                    reinterpret_cast<const ulonglong2*>(w1_0 + (u0 + u) * 48);
#pragma unroll
                for (int m = 0; m < 12; m += 2) {
                    ulonglong2 pa = __ldg(wr + m), pb = __ldg(wr + m + 1);
                    A[2 * m + 0] = ffma2(xs2, pa.x, A[2 * m + 0]);
                    A[2 * m + 1] = ffma2(xs2, pa.y, A[2 * m + 1]);
                    A[2 * m + 2] = ffma2(xs2, pb.x, A[2 * m + 2]);
                    A[2 * m + 3] = ffma2(xs2, pb.y, A[2 * m + 3]);
                }
            }
        } else if (role == 1) {
            // y1: ALL 16 v x i=0..2 -> A[i*8+p], p = v-pair (2p,2p+1)
#pragma unroll
            for (int h = 0; h < 2; ++h) {
                const float4* xp = (const float4*)(xr + 8 + 12 * h);
                float4 q0 = xp[0], q1 = xp[1], q2 = xp[2];
                float xe[12] = { q0.x,q0.y,q0.z,q0.w, q1.x,q1.y,q1.z,q1.w,
                                 q2.x,q2.y,q2.z,q2.w };
#pragma unroll
                for (int ul = 0; ul < 4; ++ul) {
                    const ulonglong2* wr =
                        (const ulonglong2*)(sm + OFF_W1 + (u0 + 4 * h + ul) * 16);
                    {
                        ulonglong2 wa = wr[0], wb = wr[1];
#pragma unroll
                        for (int i = 0; i < 3; ++i) {
                            u64 xs2 = dup2(xe[3 * ul + i]);
                            A[i * 8 + 0] = ffma2(xs2, wa.x, A[i * 8 + 0]);
                            A[i * 8 + 1] = ffma2(xs2, wa.y, A[i * 8 + 1]);
                            A[i * 8 + 2] = ffma2(xs2, wb.x, A[i * 8 + 2]);
                            A[i * 8 + 3] = ffma2(xs2, wb.y, A[i * 8 + 3]);
                        }
                    }
                    {
                        ulonglong2 wc = wr[2], wd = wr[3];
#pragma unroll
                        for (int i = 0; i < 3; ++i) {
                            u64 xs2 = dup2(xe[3 * ul + i]);
                            A[i * 8 + 4] = ffma2(xs2, wc.x, A[i * 8 + 4]);
                            A[i * 8 + 5] = ffma2(xs2, wc.y, A[i * 8 + 5]);
                            A[i * 8 + 6] = ffma2(xs2, wd.x, A[i * 8 + 6]);
                            A[i * 8 + 7] = ffma2(xs2, wd.y, A[i * 8 + 7]);
                        }
                    }
                }
            }
        } else if (role == 2) {
            // y2, i=0,1: ALL 16 v -> A[i*8+p]
#pragma unroll
            for (int h = 0; h < 2; ++h) {
                const float4* xp = (const float4*)(xr + 32 + 20 * h);
                float4 q0 = xp[0], q1 = xp[1], q2 = xp[2], q3 = xp[3], q4 = xp[4];
                float xe[20] = { q0.x,q0.y,q0.z,q0.w, q1.x,q1.y,q1.z,q1.w,
                                 q2.x,q2.y,q2.z,q2.w, q3.x,q3.y,q3.z,q3.w,
                                 q4.x,q4.y,q4.z,q4.w };
#pragma unroll
                for (int ul = 0; ul < 4; ++ul) {
                    const ulonglong2* wr =
                        (const ulonglong2*)(sm + OFF_W2 + (u0 + 4 * h + ul) * 16);
                    ulonglong2 wa = wr[0], wb = wr[1], wc = wr[2], wd = wr[3];
#pragma unroll
                    for (int i = 0; i < 2; ++i) {
                        u64 xs2 = dup2(xe[5 * ul + i]);
                        A[i * 8 + 0] = ffma2(xs2, wa.x, A[i * 8 + 0]);
                        A[i * 8 + 1] = ffma2(xs2, wa.y, A[i * 8 + 1]);
                        A[i * 8 + 2] = ffma2(xs2, wb.x, A[i * 8 + 2]);
                        A[i * 8 + 3] = ffma2(xs2, wb.y, A[i * 8 + 3]);
                        A[i * 8 + 4] = ffma2(xs2, wc.x, A[i * 8 + 4]);
                        A[i * 8 + 5] = ffma2(xs2, wc.y, A[i * 8 + 5]);
                        A[i * 8 + 6] = ffma2(xs2, wd.x, A[i * 8 + 6]);
                        A[i * 8 + 7] = ffma2(xs2, wd.y, A[i * 8 + 7]);
                    }
                }
            }
        } else {
            // y2, i=2,3,4: ALL 16 v -> A[(i-2)*8+p]; w loads split 2+2 for regs
#pragma unroll
            for (int h = 0; h < 2; ++h) {
                const float4* xp = (const float4*)(xr + 32 + 20 * h);
                float4 q0 = xp[0], q1 = xp[1], q2 = xp[2], q3 = xp[3], q4 = xp[4];
                float xe[20] = { q0.x,q0.y,q0.z,q0.w, q1.x,q1.y,q1.z,q1.w,
                                 q2.x,q2.y,q2.z,q2.w, q3.x,q3.y,q3.z,q3.w,
                                 q4.x,q4.y,q4.z,q4.w };
#pragma unroll
                for (int ul = 0; ul < 4; ++ul) {
                    const ulonglong2* wr =
                        (const ulonglong2*)(sm + OFF_W2 + (u0 + 4 * h + ul) * 16);
                    {
                        ulonglong2 wa = wr[0], wb = wr[1];
#pragma unroll
                        for (int i = 0; i < 3; ++i) {
                            u64 xs2 = dup2(xe[5 * ul + 2 + i]);
                            A[i * 8 + 0] = ffma2(xs2, wa.x, A[i * 8 + 0]);
                            A[i * 8 + 1] = ffma2(xs2, wa.y, A[i * 8 + 1]);
                            A[i * 8 + 2] = ffma2(xs2, wb.x, A[i * 8 + 2]);
                            A[i * 8 + 3] = ffma2(xs2, wb.y, A[i * 8 + 3]);
                        }
                    }
                    {
                        ulonglong2 wc = wr[2], wd = wr[3];
#pragma unroll
                        for (int i = 0; i < 3; ++i) {
                            u64 xs2 = dup2(xe[5 * ul + 2 + i]);
                            A[i * 8 + 4] = ffma2(xs2, wc.x, A[i * 8 + 4]);
                            A[i * 8 + 5] = ffma2(xs2, wc.y, A[i * 8 + 5]);
                            A[i * 8 + 6] = ffma2(xs2, wd.x, A[i * 8 + 6]);
                            A[i * 8 + 7] = ffma2(xs2, wd.y, A[i * 8 + 7]);
                        }
                    }
                }
            }
        }
    }

    // last chunk used buffer 0 (15%3==0): barrier before reusing it as gate storage
    __syncthreads();

    // ---- epilogue ----
    const float inv_in = 0.08838834764831845f;   // 1/sqrt(128)
    const int gn = node0 + node;

    // role0: o0 + gates. gates live in dead x-buffer-0 region, stride 33.
    if (role == 0) {
        float y0v[48];
#pragma unroll
        for (int j = 0; j < 24; ++j) unpack2(A[j], y0v[2 * j], y0v[2 * j + 1]);
        float o = 0.f;
#pragma unroll
        for (int h = 0; h < 16; ++h)
            o += silu(y0v[h] * inv_in) * __ldg(w2_0 + h);
#pragma unroll
        for (int v = 0; v < 16; ++v)
            sm[node * 33 + v] = silu(y0v[16 + v] * inv_in);
#pragma unroll
        for (int v = 0; v < 16; ++v)
            sm[node * 33 + 16 + v] = silu(y0v[32 + v] * inv_in);
        if (gn < n) out[gn * 9 + 0] = o * 0.25f;
    }
    __syncthreads();

    if (role == 1) {
        float o0 = 0.f, o1 = 0.f, o2 = 0.f;
#pragma unroll
        for (int p = 0; p < 8; ++p) {
            float wa = __ldg(w2_1 + 2 * p)     * sm[node * 33 + 2 * p];
            float wb = __ldg(w2_1 + 2 * p + 1) * sm[node * 33 + 2 * p + 1];
            float lo, hi;
            unpack2(A[0 * 8 + p], lo, hi); o0 += lo * wa + hi * wb;
            unpack2(A[1 * 8 + p], lo, hi); o1 += lo * wa + hi * wb;
            unpack2(A[2 * 8 + p], lo, hi); o2 += lo * wa + hi * wb;
        }
        if (gn < n) {
            const float sc = inv_in * 0.25f;
            out[gn * 9 + 1] = o0 * sc;
            out[gn * 9 + 2] = o1 * sc;
            out[gn * 9 + 3] = o2 * sc;
        }
    } else if (role == 2) {
        float o0 = 0.f, o1 = 0.f;
#pragma unroll
        for (int p = 0; p < 8; ++p) {
            float wa = __ldg(w2_2 + 2 * p)     * sm[node * 33 + 16 + 2 * p];
            float wb = __ldg(w2_2 + 2 * p + 1) * sm[node * 33 + 16 + 2 * p + 1];
            float lo, hi;
            unpack2(A[0 * 8 + p], lo, hi); o0 += lo * wa + hi * wb;
            unpack2(A[1 * 8 + p], lo, hi); o1 += lo * wa + hi * wb;
        }
        if (gn < n) {
            const float sc = inv_in * 0.25f;
            out[gn * 9 + 4] = o0 * sc;
            out[gn * 9 + 5] = o1 * sc;
        }
    } else if (role == 3) {
        float o0 = 0.f, o1 = 0.f, o2 = 0.f;
#pragma unroll
        for (int p = 0; p < 8; ++p) {
            float wa = __ldg(w2_2 + 2 * p)     * sm[node * 33 + 16 + 2 * p];
            float wb = __ldg(w2_2 + 2 * p + 1) * sm[node * 33 + 16 + 2 * p + 1];
            float lo, hi;
            unpack2(A[0 * 8 + p], lo, hi); o0 += lo * wa + hi * wb;
            unpack2(A[1 * 8 + p], lo, hi); o1 += lo * wa + hi * wb;
            unpack2(A[2 * 8 + p], lo, hi); o2 += lo * wa + hi * wb;
        }
        if (gn < n) {
            const float sc = inv_in * 0.25f;
            out[gn * 9 + 6] = o0 * sc;
            out[gn * 9 + 7] = o1 * sc;
            out[gn * 9 + 8] = o2 * sc;
        }
    }
}

extern "C" void kernel_launch(void* const* d_in, const int* in_sizes, int n_in,
                              void* d_out, int out_size)
{
    const float* x    = (const float*)d_in[0];
    const float* w1_0 = (const float*)d_in[1];
    const float* w1_1 = (const float*)d_in[2];
    const float* w1_2 = (const float*)d_in[3];
    const float* w2_0 = (const float*)d_in[4];
    const float* w2_1 = (const float*)d_in[5];
    const float* w2_2 = (const float*)d_in[6];
    float* out = (float*)d_out;

    const int n = in_sizes[0] / 1152;
    const int smem = SM_FLOATS * (int)sizeof(float);   // 103936 B
    cudaFuncSetAttribute(readout_kernel, cudaFuncAttributeMaxDynamicSharedMemorySize, smem);
    const int blocks = (n + NODES - 1) / NODES;
    readout_kernel<<<blocks, TPB, smem>>>(x, w1_0, w1_1, w1_2, w2_0, w2_1, w2_2, out, n);
}

// round 12
// speedup vs baseline: 3.8911x; 3.8911x over previous
#include <cuda_runtime.h>

#define TPB     256
#define NODES   64
#define KU      8                   // u per chunk
#define NCHUNK  16
#define XS      76                  // per node per chunk: x0(8)+x1(24)+x2(40)+pad(4)
#define XBUF    (NODES * XS)        // 4864 floats per buffer
#define OFF_W0  (3 * XBUF)          // 14592 (w1_0: 6144 floats)
#define OFF_W1  (OFF_W0 + 6144)    // 20736 (w1_1: 2048)
#define OFF_W2  (OFF_W1 + 2048)    // 22784 (w1_2: 2048)
#define SM_FLOATS (OFF_W2 + 2048)  // 24832 floats = 99328 B -> 2 blocks/SM

typedef unsigned long long u64;

__device__ __forceinline__ u64 ffma2(u64 a, u64 b, u64 c) {
    u64 d;
    asm("fma.rn.f32x2 %0, %1, %2, %3;" : "=l"(d) : "l"(a), "l"(b), "l"(c));
    return d;
}
__device__ __forceinline__ u64 dup2(float v) {
    u64 d; unsigned u = __float_as_uint(v);
    asm("mov.b64 %0, {%1, %1};" : "=l"(d) : "r"(u));
    return d;
}
__device__ __forceinline__ void unpack2(u64 a, float& lo, float& hi) {
    lo = __uint_as_float((unsigned)a);
    hi = __uint_as_float((unsigned)(a >> 32));
}
__device__ __forceinline__ float silu(float v) {
    return v / (1.f + __expf(-v));
}

__global__ void __launch_bounds__(TPB, 2)
readout_kernel(const float* __restrict__ x,
               const float* __restrict__ w1_0, const float* __restrict__ w1_1,
               const float* __restrict__ w1_2, const float* __restrict__ w2_0,
               const float* __restrict__ w2_1, const float* __restrict__ w2_2,
               float* __restrict__ out, int n)
{
    extern __shared__ float sm[];
    const int tid = threadIdx.x;
    const int node0 = blockIdx.x * NODES;
    const unsigned smbase = (unsigned)__cvta_generic_to_shared(sm);

    // ---- cp.async staging: 64 nodes x 18 float4 per chunk = 1152 over 256 thr ----
    int pk_goff[5], pk_sc[5];
    unsigned pk_dst[5];
#pragma unroll
    for (int k = 0; k < 5; ++k) {
        int f = tid + k * TPB;
        if (f >= 18 * NODES) { pk_goff[k] = -1; pk_sc[k] = 0; pk_dst[k] = 0; continue; }
        int nd = f / 18, r = f - nd * 18;
        int sb, sc, dl;
        if (r < 2)      { sb = 4 * r;             sc = 8;  dl = 4 * r; }
        else if (r < 8) { sb = 128 + 4 * (r - 2); sc = 24; dl = 8 + 4 * (r - 2); }
        else            { sb = 512 + 4 * (r - 8); sc = 40; dl = 32 + 4 * (r - 8); }
        int gn = node0 + nd;
        if (gn >= n) gn = n - 1;                 // clamp; output stores are guarded
        pk_goff[k] = gn * 1152 + sb;
        pk_sc[k]   = sc;
        pk_dst[k]  = (unsigned)((nd * XS + dl) * 4);
    }
    auto stage = [&](int c, int buf) {
#pragma unroll
        for (int k = 0; k < 5; ++k) {
            if (pk_goff[k] < 0) break;
            const float* src = x + pk_goff[k] + pk_sc[k] * c;
            unsigned dst = smbase + (unsigned)(buf * (XBUF * 4)) + pk_dst[k];
            asm volatile("cp.async.cg.shared.global [%0], [%1], 16;"
                         :: "r"(dst), "l"(src));
        }
    };

    // two chunks in flight before any compute (R5's proven pipeline)
    stage(0, 0); asm volatile("cp.async.commit_group;" ::: "memory");
    stage(1, 1); asm volatile("cp.async.commit_group;" ::: "memory");

    // ALL weights to smem (R11 lesson: L1D is gone at this smem size)
    for (int i = tid; i < 6144; i += TPB) sm[OFF_W0 + i] = w1_0[i];
    for (int i = tid; i < 2048; i += TPB) sm[OFF_W1 + i] = w1_1[i];
    for (int i = tid; i < 2048; i += TPB) sm[OFF_W2 + i] = w1_2[i];

    // 8 warps = 2 groups x 4 roles, redundancy-1.
    // role = (s + 2g) & 3 -> each SMSP gets 2 different roles: balanced issue.
    const int w    = tid >> 5;
    const int lane = tid & 31;
    const int s    = w & 3;
    const int g    = w >> 2;
    const int role = (s + 2 * g) & 3;   // 0:y0(48v) 1:y1(16v x3i) 2:y2 i01 3:y2 i234
    const int node = g * 32 + lane;

    u64 A[24];
#pragma unroll
    for (int i = 0; i < 24; ++i) A[i] = 0ull;

#pragma unroll 1
    for (int c = 0; c < NCHUNK; ++c) {
        if (c == NCHUNK - 1) asm volatile("cp.async.wait_group 0;" ::: "memory");
        else                 asm volatile("cp.async.wait_group 1;" ::: "memory");
        __syncthreads();
        if (c + 2 < NCHUNK) {
            stage(c + 2, (c + 2) % 3);      // overwrites buffer (c-1)%3: safe past barrier
            asm volatile("cp.async.commit_group;" ::: "memory");
        }
        const float* xr = sm + (c % 3) * XBUF + node * XS;
        const int u0 = KU * c;

        if (role == 0) {
            // y0: ALL 48 outputs as 24 f32x2 pairs; weights broadcast from smem
            float4 xa = *(const float4*)xr;
            float4 xb = *(const float4*)(xr + 4);
            float xe[8] = { xa.x, xa.y, xa.z, xa.w, xb.x, xb.y, xb.z, xb.w };
#pragma unroll
            for (int u = 0; u < 8; ++u) {
                u64 xs2 = dup2(xe[u]);
                const ulonglong2* wr =
                    (const ulonglong2*)(sm + OFF_W0 + (u0 + u) * 48);
#pragma unroll
                for (int m = 0; m < 12; m += 2) {
                    ulonglong2 pa = wr[m], pb = wr[m + 1];
                    A[2 * m + 0] = ffma2(xs2, pa.x, A[2 * m + 0]);
                    A[2 * m + 1] = ffma2(xs2, pa.y, A[2 * m + 1]);
                    A[2 * m + 2] = ffma2(xs2, pb.x, A[2 * m + 2]);
                    A[2 * m + 3] = ffma2(xs2, pb.y, A[2 * m + 3]);
                }
            }
        } else if (role == 1) {
            // y1: ALL 16 v x i=0..2 -> A[i*8+p], p = v-pair (2p,2p+1)
#pragma unroll
            for (int h = 0; h < 2; ++h) {
                const float4* xp = (const float4*)(xr + 8 + 12 * h);
                float4 q0 = xp[0], q1 = xp[1], q2 = xp[2];
                float xe[12] = { q0.x,q0.y,q0.z,q0.w, q1.x,q1.y,q1.z,q1.w,
                                 q2.x,q2.y,q2.z,q2.w };
#pragma unroll
                for (int ul = 0; ul < 4; ++ul) {
                    const ulonglong2* wr =
                        (const ulonglong2*)(sm + OFF_W1 + (u0 + 4 * h + ul) * 16);
                    ulonglong2 wa = wr[0], wb = wr[1], wc = wr[2], wd = wr[3];
#pragma unroll
                    for (int i = 0; i < 3; ++i) {
                        u64 xs2 = dup2(xe[3 * ul + i]);
                        A[i * 8 + 0] = ffma2(xs2, wa.x, A[i * 8 + 0]);
                        A[i * 8 + 1] = ffma2(xs2, wa.y, A[i * 8 + 1]);
                        A[i * 8 + 2] = ffma2(xs2, wb.x, A[i * 8 + 2]);
                        A[i * 8 + 3] = ffma2(xs2, wb.y, A[i * 8 + 3]);
                        A[i * 8 + 4] = ffma2(xs2, wc.x, A[i * 8 + 4]);
                        A[i * 8 + 5] = ffma2(xs2, wc.y, A[i * 8 + 5]);
                        A[i * 8 + 6] = ffma2(xs2, wd.x, A[i * 8 + 6]);
                        A[i * 8 + 7] = ffma2(xs2, wd.y, A[i * 8 + 7]);
                    }
                }
            }
        } else if (role == 2) {
            // y2, i=0,1: ALL 16 v -> A[i*8+p]
#pragma unroll
            for (int h = 0; h < 2; ++h) {
                const float4* xp = (const float4*)(xr + 32 + 20 * h);
                float4 q0 = xp[0], q1 = xp[1], q2 = xp[2], q3 = xp[3], q4 = xp[4];
                float xe[20] = { q0.x,q0.y,q0.z,q0.w, q1.x,q1.y,q1.z,q1.w,
                                 q2.x,q2.y,q2.z,q2.w, q3.x,q3.y,q3.z,q3.w,
                                 q4.x,q4.y,q4.z,q4.w };
#pragma unroll
                for (int ul = 0; ul < 4; ++ul) {
                    const ulonglong2* wr =
                        (const ulonglong2*)(sm + OFF_W2 + (u0 + 4 * h + ul) * 16);
                    ulonglong2 wa = wr[0], wb = wr[1], wc = wr[2], wd = wr[3];
#pragma unroll
                    for (int i = 0; i < 2; ++i) {
                        u64 xs2 = dup2(xe[5 * ul + i]);
                        A[i * 8 + 0] = ffma2(xs2, wa.x, A[i * 8 + 0]);
                        A[i * 8 + 1] = ffma2(xs2, wa.y, A[i * 8 + 1]);
                        A[i * 8 + 2] = ffma2(xs2, wb.x, A[i * 8 + 2]);
                        A[i * 8 + 3] = ffma2(xs2, wb.y, A[i * 8 + 3]);
                        A[i * 8 + 4] = ffma2(xs2, wc.x, A[i * 8 + 4]);
                        A[i * 8 + 5] = ffma2(xs2, wc.y, A[i * 8 + 5]);
                        A[i * 8 + 6] = ffma2(xs2, wd.x, A[i * 8 + 6]);
                        A[i * 8 + 7] = ffma2(xs2, wd.y, A[i * 8 + 7]);
                    }
                }
            }
        } else {
            // y2, i=2,3,4: ALL 16 v -> A[(i-2)*8+p]
#pragma unroll
            for (int h = 0; h < 2; ++h) {
                const float4* xp = (const float4*)(xr + 32 + 20 * h);
                float4 q0 = xp[0], q1 = xp[1], q2 = xp[2], q3 = xp[3], q4 = xp[4];
                float xe[20] = { q0.x,q0.y,q0.z,q0.w, q1.x,q1.y,q1.z,q1.w,
                                 q2.x,q2.y,q2.z,q2.w, q3.x,q3.y,q3.z,q3.w,
                                 q4.x,q4.y,q4.z,q4.w };
#pragma unroll
                for (int ul = 0; ul < 4; ++ul) {
                    const ulonglong2* wr =
                        (const ulonglong2*)(sm + OFF_W2 + (u0 + 4 * h + ul) * 16);
                    ulonglong2 wa = wr[0], wb = wr[1], wc = wr[2], wd = wr[3];
#pragma unroll
                    for (int i = 0; i < 3; ++i) {
                        u64 xs2 = dup2(xe[5 * ul + 2 + i]);
                        A[i * 8 + 0] = ffma2(xs2, wa.x, A[i * 8 + 0]);
                        A[i * 8 + 1] = ffma2(xs2, wa.y, A[i * 8 + 1]);
                        A[i * 8 + 2] = ffma2(xs2, wb.x, A[i * 8 + 2]);
                        A[i * 8 + 3] = ffma2(xs2, wb.y, A[i * 8 + 3]);
                        A[i * 8 + 4] = ffma2(xs2, wc.x, A[i * 8 + 4]);
                        A[i * 8 + 5] = ffma2(xs2, wc.y, A[i * 8 + 5]);
                        A[i * 8 + 6] = ffma2(xs2, wd.x, A[i * 8 + 6]);
                        A[i * 8 + 7] = ffma2(xs2, wd.y, A[i * 8 + 7]);
                    }
                }
            }
        }
    }

    // last chunk used buffer 0 (15%3==0): barrier before reusing it as gate storage
    __syncthreads();

    // ---- epilogue ----
    const float inv_in = 0.08838834764831845f;   // 1/sqrt(128)
    const int gn = node0 + node;

    // role0: o0 + gates. gates live in dead x-buffer-0 region, stride 33.
    if (role == 0) {
        float y0v[48];
#pragma unroll
        for (int j = 0; j < 24; ++j) unpack2(A[j], y0v[2 * j], y0v[2 * j + 1]);
        float o = 0.f;
#pragma unroll
        for (int h = 0; h < 16; ++h)
            o += silu(y0v[h] * inv_in) * __ldg(w2_0 + h);
#pragma unroll
        for (int v = 0; v < 16; ++v)
            sm[node * 33 + v] = silu(y0v[16 + v] * inv_in);
#pragma unroll
        for (int v = 0; v < 16; ++v)
            sm[node * 33 + 16 + v] = silu(y0v[32 + v] * inv_in);
        if (gn < n) out[gn * 9 + 0] = o * 0.25f;
    }
    __syncthreads();

    if (role == 1) {
        float o0 = 0.f, o1 = 0.f, o2 = 0.f;
#pragma unroll
        for (int p = 0; p < 8; ++p) {
            float wa = __ldg(w2_1 + 2 * p)     * sm[node * 33 + 2 * p];
            float wb = __ldg(w2_1 + 2 * p + 1) * sm[node * 33 + 2 * p + 1];
            float lo, hi;
            unpack2(A[0 * 8 + p], lo, hi); o0 += lo * wa + hi * wb;
            unpack2(A[1 * 8 + p], lo, hi); o1 += lo * wa + hi * wb;
            unpack2(A[2 * 8 + p], lo, hi); o2 += lo * wa + hi * wb;
        }
        if (gn < n) {
            const float sc = inv_in * 0.25f;
            out[gn * 9 + 1] = o0 * sc;
            out[gn * 9 + 2] = o1 * sc;
            out[gn * 9 + 3] = o2 * sc;
        }
    } else if (role == 2) {
        float o0 = 0.f, o1 = 0.f;
#pragma unroll
        for (int p = 0; p < 8; ++p) {
            float wa = __ldg(w2_2 + 2 * p)     * sm[node * 33 + 16 + 2 * p];
            float wb = __ldg(w2_2 + 2 * p + 1) * sm[node * 33 + 16 + 2 * p + 1];
            float lo, hi;
            unpack2(A[0 * 8 + p], lo, hi); o0 += lo * wa + hi * wb;
            unpack2(A[1 * 8 + p], lo, hi); o1 += lo * wa + hi * wb;
        }
        if (gn < n) {
            const float sc = inv_in * 0.25f;
            out[gn * 9 + 4] = o0 * sc;
            out[gn * 9 + 5] = o1 * sc;
        }
    } else if (role == 3) {
        float o0 = 0.f, o1 = 0.f, o2 = 0.f;
#pragma unroll
        for (int p = 0; p < 8; ++p) {
            float wa = __ldg(w2_2 + 2 * p)     * sm[node * 33 + 16 + 2 * p];
            float wb = __ldg(w2_2 + 2 * p + 1) * sm[node * 33 + 16 + 2 * p + 1];
            float lo, hi;
            unpack2(A[0 * 8 + p], lo, hi); o0 += lo * wa + hi * wb;
            unpack2(A[1 * 8 + p], lo, hi); o1 += lo * wa + hi * wb;
            unpack2(A[2 * 8 + p], lo, hi); o2 += lo * wa + hi * wb;
        }
        if (gn < n) {
            const float sc = inv_in * 0.25f;
            out[gn * 9 + 6] = o0 * sc;
            out[gn * 9 + 7] = o1 * sc;
            out[gn * 9 + 8] = o2 * sc;
        }
    }
}

extern "C" void kernel_launch(void* const* d_in, const int* in_sizes, int n_in,
                              void* d_out, int out_size)
{
    const float* x    = (const float*)d_in[0];
    const float* w1_0 = (const float*)d_in[1];
    const float* w1_1 = (const float*)d_in[2];
    const float* w1_2 = (const float*)d_in[3];
    const float* w2_0 = (const float*)d_in[4];
    const float* w2_1 = (const float*)d_in[5];
    const float* w2_2 = (const float*)d_in[6];
    float* out = (float*)d_out;

    const int n = in_sizes[0] / 1152;
    const int smem = SM_FLOATS * (int)sizeof(float);   // 99328 B
    cudaFuncSetAttribute(readout_kernel, cudaFuncAttributeMaxDynamicSharedMemorySize, smem);
    const int blocks = (n + NODES - 1) / NODES;
    readout_kernel<<<blocks, TPB, smem>>>(x, w1_0, w1_1, w1_2, w2_0, w2_1, w2_2, out, n);
}